// round 16
// baseline (speedup 1.0000x reference)
#include <cuda_runtime.h>
#include <cuda_fp16.h>
#include <cstdint>

#define N_NODES 50000
#define N_EDGES 800000
#define IN_CH   512
#define HID     256

// ---------------- scratch (no allocations allowed) ----------------
#define NB_SCAN ((N_NODES + 255) / 256)   // 196

__device__ int      g_degi  [N_NODES];
__device__ float    g_dinv  [N_NODES];
__device__ int      g_rowptr[N_NODES + 1];
__device__ int      g_fill  [N_NODES];
__device__ int      g_bsum  [NB_SCAN];
__device__ int      g_boff  [NB_SCAN];
__device__ int2     g_epack [N_EDGES];                   // {src, norm bits}
__device__ __half   g_w0h   [IN_CH * HID];               // fp16 W0^T  [n][k]
__device__ __half   g_w1h   [HID * HID];                 // fp16 W1^T
__device__ __half   g_w2h   [HID * HID];                 // fp16 W2^T
__device__ __half   g_h     [(size_t)N_NODES * HID];     // GEMM output (gather operand)
__device__ __half   g_in    [(size_t)N_NODES * HID];     // fp16 relu(agg+b)

// ---------------- degree / norm / CSR build ----------------
__global__ void zero_kernel() {
    int i = blockIdx.x * blockDim.x + threadIdx.x;
    if (i < N_NODES) { g_degi[i] = 0; g_fill[i] = 0; }
}

__global__ void deg_count_kernel(const int* __restrict__ dst) {
    int e = blockIdx.x * blockDim.x + threadIdx.x;
    if (e < N_EDGES) atomicAdd(&g_degi[__ldg(&dst[e])], 1);
}

// block sums for scan + dinv (deg final after deg_count)
__global__ void scan_bsum_kernel() {
    __shared__ int sh[256];
    int t = threadIdx.x;
    int i = blockIdx.x * 256 + t;
    int d = (i < N_NODES) ? g_degi[i] : 0;
    if (i < N_NODES) g_dinv[i] = rsqrtf((float)(d + 1));   // +1 self-loop
    sh[t] = d;
    __syncthreads();
    for (int off = 128; off > 0; off >>= 1) {
        if (t < off) sh[t] += sh[t + off];
        __syncthreads();
    }
    if (t == 0) g_bsum[blockIdx.x] = sh[0];
}

__global__ void scan_boff_kernel() {
    __shared__ int sh[256];
    int t = threadIdx.x;
    int v = (t < NB_SCAN) ? g_bsum[t] : 0;
    sh[t] = v;
    __syncthreads();
    for (int off = 1; off < 256; off <<= 1) {
        int u = (t >= off) ? sh[t - off] : 0;
        __syncthreads();
        sh[t] += u;
        __syncthreads();
    }
    if (t < NB_SCAN) g_boff[t] = sh[t] - v;
    if (t == 255) g_rowptr[N_NODES] = sh[255];
}

__global__ void scan_apply_kernel() {
    __shared__ int sh[256];
    int t = threadIdx.x;
    int i = blockIdx.x * 256 + t;
    int v = (i < N_NODES) ? g_degi[i] : 0;
    sh[t] = v;
    __syncthreads();
    for (int off = 1; off < 256; off <<= 1) {
        int u = (t >= off) ? sh[t - off] : 0;
        __syncthreads();
        sh[t] += u;
        __syncthreads();
    }
    if (i < N_NODES) g_rowptr[i] = g_boff[blockIdx.x] + sh[t] - v;
}

__global__ void scatter_kernel(const int* __restrict__ src,
                               const int* __restrict__ dst) {
    int e = blockIdx.x * blockDim.x + threadIdx.x;
    if (e < N_EDGES) {
        int s = __ldg(&src[e]);
        int d = __ldg(&dst[e]);
        int pos = g_rowptr[d] + atomicAdd(&g_fill[d], 1);
        g_epack[pos] = make_int2(s, __float_as_int(g_dinv[s] * g_dinv[d]));
    }
}

// ---------------- weight transpose + fp16 ----------------
__global__ void cvt_w_kernel(const float* __restrict__ W0,
                             const float* __restrict__ W1,
                             const float* __restrict__ W2) {
    int i = blockIdx.x * blockDim.x + threadIdx.x;
    if (i < IN_CH * HID) {
        int n = i / IN_CH, k = i % IN_CH;
        g_w0h[i] = __float2half(__ldg(&W0[k * HID + n]));
    }
    if (i < HID * HID) {
        int n = i / HID, k = i % HID;
        g_w1h[i] = __float2half(__ldg(&W1[k * HID + n]));
        g_w2h[i] = __float2half(__ldg(&W2[k * HID + n]));
    }
}

// ---------------- fp16 mma m16n8k16 + ldmatrix ----------------
__device__ __forceinline__ void mma_f16(float* c,
                                        uint32_t a0, uint32_t a1, uint32_t a2, uint32_t a3,
                                        uint32_t b0, uint32_t b1) {
    asm volatile(
        "mma.sync.aligned.m16n8k16.row.col.f32.f16.f16.f32 "
        "{%0,%1,%2,%3}, {%4,%5,%6,%7}, {%8,%9}, {%0,%1,%2,%3};"
        : "+f"(c[0]), "+f"(c[1]), "+f"(c[2]), "+f"(c[3])
        : "r"(a0), "r"(a1), "r"(a2), "r"(a3), "r"(b0), "r"(b1));
}

__device__ __forceinline__ void ldsm_x4(uint32_t* r, uint32_t addr) {
    asm volatile("ldmatrix.sync.aligned.m8n8.x4.shared.b16 {%0,%1,%2,%3}, [%4];"
                 : "=r"(r[0]), "=r"(r[1]), "=r"(r[2]), "=r"(r[3]) : "r"(addr));
}

// ---------------- fp16 GEMM, full-N CTA, 3-stage cp.async + ldmatrix ----------------
// C[rows row0.., 256] = A[M,K] * Wt[256,K]^T.  CTA: 128 rows x 256 cols, 512 threads.
// AF32 variant stages raw fp32 A and converts to fp16 in smem (layer 0).
#define GBM 128
#define GBK 32
#define TSH 40                                // halves per smem row (80 B), conflict-free
#define A_TILE_B (128 * TSH * 2)              // 10240
#define B_TILE_B (256 * TSH * 2)              // 20480
#define BBASE (3 * A_TILE_B)                  // 30720
#define SCR_BASE (BBASE + 3 * B_TILE_B)       // 92160
#define SCR_STRIDE 144                        // bytes per fp32 scratch row (16B mult)
#define SCR_TILE (128 * SCR_STRIDE)           // 18432
#define GEMM_SMEM_F16 SCR_BASE                // 92160
#define GEMM_SMEM_F32 (SCR_BASE + 3 * SCR_TILE)   // 147456

template <bool AF32>
__global__ __launch_bounds__(512) void gemm_f16_kernel(
    int K, int row0,
    const void* __restrict__ Aptr,    // [M, K] fp32 (AF32) or fp16
    const __half* __restrict__ Wt,    // [256, K]
    __half* __restrict__ Ch)          // [M, 256]
{
    extern __shared__ char smc[];
    const uint32_t sbase = (uint32_t)__cvta_generic_to_shared(smc);

    const int tid  = threadIdx.x;
    const int lane = tid & 31;
    const int warp = tid >> 5;
    const int wm   = warp >> 3;          // 0..1
    const int wn   = warp & 7;           // 0..7
    const int g    = lane >> 2;          // 0..7  (epilogue row)
    const int t    = lane & 3;           // 0..3  (epilogue col pair)
    const int lrow = lane & 7;
    const int lgrp = lane >> 3;

    const int crow0 = row0 + blockIdx.x * GBM;

    float acc[4][4][4];
#pragma unroll
    for (int fm = 0; fm < 4; fm++)
#pragma unroll
        for (int fn = 0; fn < 4; fn++)
#pragma unroll
            for (int q = 0; q < 4; q++) acc[fm][fn][q] = 0.0f;

    uint32_t aOff[4];
#pragma unroll
    for (int fm = 0; fm < 4; fm++)
        aOff[fm] = (uint32_t)(((wm * 64 + fm * 16 + ((lgrp & 1) << 3) + lrow) * TSH +
                               ((lgrp >> 1) << 3)) * 2);
    uint32_t bOff[2];
#pragma unroll
    for (int p = 0; p < 2; p++)
        bOff[p] = (uint32_t)(((wn * 32 + p * 16 + ((lgrp >> 1) << 3) + lrow) * TSH +
                              ((lgrp & 1) << 3)) * 2);

    auto stage = [&](int buf, int k0) {
        if (AF32) {
            const float* A32 = (const float*)Aptr;
#pragma unroll
            for (int i = 0; i < 2; i++) {
                int idx   = tid + i * 512;
                int row   = idx >> 3;
                int chunk = idx & 7;
                int grow  = crow0 + row;
                uint32_t dstp = sbase + (uint32_t)(SCR_BASE + buf * SCR_TILE + row * SCR_STRIDE + chunk * 16);
                const float* srcp = A32 + (size_t)(grow < N_NODES ? grow : 0) * K + k0 + chunk * 4;
                int sz = (grow < N_NODES) ? 16 : 0;
                asm volatile("cp.async.ca.shared.global [%0], [%1], 16, %2;"
                             :: "r"(dstp), "l"(srcp), "r"(sz));
            }
        } else {
            const __half* A16 = (const __half*)Aptr;
            int row   = tid >> 2;
            int chunk = tid & 3;
            int grow  = crow0 + row;
            uint32_t dstp = sbase + (uint32_t)(buf * A_TILE_B + row * (TSH * 2) + chunk * 16);
            const __half* srcp = A16 + (size_t)(grow < N_NODES ? grow : 0) * K + k0 + chunk * 8;
            int sz = (grow < N_NODES) ? 16 : 0;
            asm volatile("cp.async.ca.shared.global [%0], [%1], 16, %2;"
                         :: "r"(dstp), "l"(srcp), "r"(sz));
        }
#pragma unroll
        for (int i = 0; i < 2; i++) {
            int idx   = tid + i * 512;
            int row   = idx >> 2;
            int chunk = idx & 3;
            uint32_t dstp = sbase + (uint32_t)(BBASE + buf * B_TILE_B + row * (TSH * 2) + chunk * 16);
            const __half* srcp = Wt + (size_t)row * K + k0 + chunk * 8;
            asm volatile("cp.async.ca.shared.global [%0], [%1], 16;"
                         :: "r"(dstp), "l"(srcp));
        }
        asm volatile("cp.async.commit_group;");
    };

    const int nk = K / GBK;        // 16 (layer 0) or 8
    stage(0, 0);
    stage(1, GBK);

    for (int ki = 0; ki < nk; ki++) {
        const int buf = ki % 3;
        if (ki + 1 < nk) {
            asm volatile("cp.async.wait_group 1;");
        } else {
            asm volatile("cp.async.wait_group 0;");
        }
        __syncthreads();

        if (AF32) {
            // convert scratch fp32 -> fp16 A tile for this buffer
            int row   = tid >> 2;
            int chunk = tid & 3;          // 8 halves per task
            const float* sp = reinterpret_cast<const float*>(smc + SCR_BASE + buf * SCR_TILE +
                                                             row * SCR_STRIDE) + chunk * 8;
            float4 v0 = *reinterpret_cast<const float4*>(sp);
            float4 v1 = *reinterpret_cast<const float4*>(sp + 4);
            __half2 h0 = __floats2half2_rn(v0.x, v0.y);
            __half2 h1 = __floats2half2_rn(v0.z, v0.w);
            __half2 h2 = __floats2half2_rn(v1.x, v1.y);
            __half2 h3 = __floats2half2_rn(v1.z, v1.w);
            uint4 u;
            u.x = *reinterpret_cast<uint32_t*>(&h0);
            u.y = *reinterpret_cast<uint32_t*>(&h1);
            u.z = *reinterpret_cast<uint32_t*>(&h2);
            u.w = *reinterpret_cast<uint32_t*>(&h3);
            *reinterpret_cast<uint4*>(smc + buf * A_TILE_B + row * (TSH * 2) + chunk * 16) = u;
            __syncthreads();
        }

        if (ki + 2 < nk) stage((ki + 2) % 3, (ki + 2) * GBK);

        const uint32_t aBase = sbase + (uint32_t)(buf * A_TILE_B);
        const uint32_t bBase = sbase + (uint32_t)(BBASE + buf * B_TILE_B);

#pragma unroll
        for (int kc = 0; kc < 2; kc++) {
            const uint32_t kb = kc * 32;     // 16 halves = 32 bytes
            uint32_t a[4][4];
            uint32_t b[2][4];
#pragma unroll
            for (int fm = 0; fm < 4; fm++) ldsm_x4(a[fm], aBase + aOff[fm] + kb);
#pragma unroll
            for (int p = 0; p < 2; p++)    ldsm_x4(b[p], bBase + bOff[p] + kb);
#pragma unroll
            for (int fm = 0; fm < 4; fm++)
#pragma unroll
                for (int fn = 0; fn < 4; fn++)
                    mma_f16(acc[fm][fn],
                            a[fm][0], a[fm][1], a[fm][2], a[fm][3],
                            b[fn >> 1][(fn & 1) * 2], b[fn >> 1][(fn & 1) * 2 + 1]);
        }
    }
    __syncthreads();

    // Epilogue: fp16 stores (half2, c even)
#pragma unroll
    for (int fm = 0; fm < 4; fm++) {
        int r0 = crow0 + wm * 64 + fm * 16 + g;
        int r1 = r0 + 8;
#pragma unroll
        for (int fn = 0; fn < 4; fn++) {
            int c = wn * 32 + fn * 8 + 2 * t;
            if (r0 < N_NODES)
                *reinterpret_cast<__half2*>(Ch + (size_t)r0 * HID + c) =
                    __floats2half2_rn(acc[fm][fn][0], acc[fm][fn][1]);
            if (r1 < N_NODES)
                *reinterpret_cast<__half2*>(Ch + (size_t)r1 * HID + c) =
                    __floats2half2_rn(acc[fm][fn][2], acc[fm][fn][3]);
        }
    }
}

// ---------------- CSR gather (packed edges, 4x-unrolled) ----------------
__device__ __forceinline__ void agg_node(int node, const __half* __restrict__ h,
                                         int lane, float acc[8]) {
#pragma unroll
    for (int q = 0; q < 8; q++) acc[q] = 0.0f;

    int p0 = g_rowptr[node];
    int p1 = g_rowptr[node + 1];
    for (int base = p0; base < p1; base += 32) {
        int nn = min(32, p1 - base);
        int2 ep = make_int2(0, 0);
        if (base + lane < p1) ep = __ldg(&g_epack[base + lane]);
        int   sv = ep.x;
        float nv = __int_as_float(ep.y);

        int j = 0;
        for (; j + 4 <= nn; j += 4) {
            int   s0 = __shfl_sync(0xffffffffu, sv, j);
            int   s1 = __shfl_sync(0xffffffffu, sv, j + 1);
            int   s2 = __shfl_sync(0xffffffffu, sv, j + 2);
            int   s3 = __shfl_sync(0xffffffffu, sv, j + 3);
            float n0 = __shfl_sync(0xffffffffu, nv, j);
            float n1 = __shfl_sync(0xffffffffu, nv, j + 1);
            float n2 = __shfl_sync(0xffffffffu, nv, j + 2);
            float n3 = __shfl_sync(0xffffffffu, nv, j + 3);
            uint4 r0 = __ldg(reinterpret_cast<const uint4*>(h + (size_t)s0 * HID) + lane);
            uint4 r1 = __ldg(reinterpret_cast<const uint4*>(h + (size_t)s1 * HID) + lane);
            uint4 r2 = __ldg(reinterpret_cast<const uint4*>(h + (size_t)s2 * HID) + lane);
            uint4 r3 = __ldg(reinterpret_cast<const uint4*>(h + (size_t)s3 * HID) + lane);
            const __half2* v0 = reinterpret_cast<const __half2*>(&r0);
            const __half2* v1 = reinterpret_cast<const __half2*>(&r1);
            const __half2* v2 = reinterpret_cast<const __half2*>(&r2);
            const __half2* v3 = reinterpret_cast<const __half2*>(&r3);
#pragma unroll
            for (int q = 0; q < 4; q++) {
                float2 f0 = __half22float2(v0[q]);
                float2 f1 = __half22float2(v1[q]);
                float2 f2 = __half22float2(v2[q]);
                float2 f3 = __half22float2(v3[q]);
                acc[2 * q + 0] = fmaf(n0, f0.x, fmaf(n1, f1.x, fmaf(n2, f2.x, fmaf(n3, f3.x, acc[2 * q + 0]))));
                acc[2 * q + 1] = fmaf(n0, f0.y, fmaf(n1, f1.y, fmaf(n2, f2.y, fmaf(n3, f3.y, acc[2 * q + 1]))));
            }
        }
        for (; j < nn; j++) {
            int   s   = __shfl_sync(0xffffffffu, sv, j);
            float nrm = __shfl_sync(0xffffffffu, nv, j);
            uint4 raw = __ldg(reinterpret_cast<const uint4*>(h + (size_t)s * HID) + lane);
            const __half2* hv = reinterpret_cast<const __half2*>(&raw);
#pragma unroll
            for (int q = 0; q < 4; q++) {
                float2 f = __half22float2(hv[q]);
                acc[2 * q + 0] = fmaf(nrm, f.x, acc[2 * q + 0]);
                acc[2 * q + 1] = fmaf(nrm, f.y, acc[2 * q + 1]);
            }
        }
    }
    // self-loop
    float d = g_dinv[node];
    float w = d * d;
    uint4 raw = __ldg(reinterpret_cast<const uint4*>(h + (size_t)node * HID) + lane);
    const __half2* hv = reinterpret_cast<const __half2*>(&raw);
#pragma unroll
    for (int q = 0; q < 4; q++) {
        float2 f = __half22float2(hv[q]);
        acc[2 * q + 0] = fmaf(w, f.x, acc[2 * q + 0]);
        acc[2 * q + 1] = fmaf(w, f.y, acc[2 * q + 1]);
    }
}

// out = fp16(relu(agg + b)) over node range [node0, node1)
__global__ void agg_relu_kernel(int node0, int node1,
                                const __half* __restrict__ h,
                                const float* __restrict__ b,
                                __half* __restrict__ outbuf) {
    int gtid = blockIdx.x * blockDim.x + threadIdx.x;
    int node = node0 + (gtid >> 5);
    int lane = threadIdx.x & 31;
    if (node >= node1) return;

    float acc[8];
    agg_node(node, h, lane, acc);

    const float4* bp = reinterpret_cast<const float4*>(b);
    float4 b0 = __ldg(&bp[2 * lane]);
    float4 b1 = __ldg(&bp[2 * lane + 1]);

    __half2 h0 = __floats2half2_rn(fmaxf(acc[0] + b0.x, 0.f), fmaxf(acc[1] + b0.y, 0.f));
    __half2 h1 = __floats2half2_rn(fmaxf(acc[2] + b0.z, 0.f), fmaxf(acc[3] + b0.w, 0.f));
    __half2 h2 = __floats2half2_rn(fmaxf(acc[4] + b1.x, 0.f), fmaxf(acc[5] + b1.y, 0.f));
    __half2 h3 = __floats2half2_rn(fmaxf(acc[6] + b1.z, 0.f), fmaxf(acc[7] + b1.w, 0.f));

    uint4 u;
    u.x = *reinterpret_cast<uint32_t*>(&h0);
    u.y = *reinterpret_cast<uint32_t*>(&h1);
    u.z = *reinterpret_cast<uint32_t*>(&h2);
    u.w = *reinterpret_cast<uint32_t*>(&h3);
    reinterpret_cast<uint4*>(outbuf + (size_t)node * HID)[lane] = u;
}

__global__ void agg_readout_kernel(const __half* __restrict__ h,
                                   const float* __restrict__ b,
                                   const float* __restrict__ Wout,
                                   const float* __restrict__ bout,
                                   float* __restrict__ out) {
    int gtid = blockIdx.x * blockDim.x + threadIdx.x;
    int node = gtid >> 5;
    int lane = threadIdx.x & 31;
    if (node >= N_NODES) return;

    float acc[8];
    agg_node(node, h, lane, acc);

    const float4* bp = reinterpret_cast<const float4*>(b);
    const float4* wp = reinterpret_cast<const float4*>(Wout);
    float4 b0 = __ldg(&bp[2 * lane]);
    float4 b1 = __ldg(&bp[2 * lane + 1]);
    float4 w0 = __ldg(&wp[2 * lane]);
    float4 w1 = __ldg(&wp[2 * lane + 1]);

    float s = fmaxf(acc[0] + b0.x, 0.f) * w0.x + fmaxf(acc[1] + b0.y, 0.f) * w0.y +
              fmaxf(acc[2] + b0.z, 0.f) * w0.z + fmaxf(acc[3] + b0.w, 0.f) * w0.w +
              fmaxf(acc[4] + b1.x, 0.f) * w1.x + fmaxf(acc[5] + b1.y, 0.f) * w1.y +
              fmaxf(acc[6] + b1.z, 0.f) * w1.z + fmaxf(acc[7] + b1.w, 0.f) * w1.w;
#pragma unroll
    for (int o = 16; o > 0; o >>= 1) s += __shfl_down_sync(0xffffffffu, s, o);
    if (lane == 0) out[node] = s + __ldg(&bout[0]);
}

// ---------------- host launcher ----------------
#define CHUNK 25088                           // 196 GEMM blocks worth of rows

extern "C" void kernel_launch(void* const* d_in, const int* in_sizes, int n_in,
                              void* d_out, int out_size) {
    const float* x    = (const float*)d_in[0];
    const int*   ei   = (const int*)d_in[1];   // delivered as int32
    const float* W0   = (const float*)d_in[2];
    const float* b0   = (const float*)d_in[3];
    const float* W1   = (const float*)d_in[4];
    const float* b1   = (const float*)d_in[5];
    const float* W2   = (const float*)d_in[6];
    const float* b2   = (const float*)d_in[7];
    const float* Wout = (const float*)d_in[8];
    const float* bout = (const float*)d_in[9];
    float*       out  = (float*)d_out;

    const int* src = ei;             // edge_index[0]
    const int* dst = ei + N_EDGES;   // edge_index[1]

    __half *p_h, *p_in, *p_w0h, *p_w1h, *p_w2h;
    cudaGetSymbolAddress((void**)&p_h,   g_h);
    cudaGetSymbolAddress((void**)&p_in,  g_in);
    cudaGetSymbolAddress((void**)&p_w0h, g_w0h);
    cudaGetSymbolAddress((void**)&p_w1h, g_w1h);
    cudaGetSymbolAddress((void**)&p_w2h, g_w2h);
    (void)in_sizes; (void)n_in; (void)out_size;

    cudaFuncSetAttribute(gemm_f16_kernel<true>,
                         cudaFuncAttributeMaxDynamicSharedMemorySize, GEMM_SMEM_F32);
    cudaFuncSetAttribute(gemm_f16_kernel<false>,
                         cudaFuncAttributeMaxDynamicSharedMemorySize, GEMM_SMEM_F16);

    const int T = 256;
    const int nodeBlocks = (N_NODES + T - 1) / T;
    const int edgeBlocks = (N_EDGES + T - 1) / T;
    const int warpBlocks = (N_NODES * 32 + T - 1) / T;
    const int gemmGrid   = (N_NODES + GBM - 1) / GBM;   // 391

    // agg chunk grids
    const int aggBlocks0 = (CHUNK * 32 + T - 1) / T;                    // 3136
    const int aggBlocks1 = ((N_NODES - CHUNK) * 32 + T - 1) / T;        // 3114
    const int gemmGrid0  = CHUNK / GBM;                                 // 196
    const int gemmGrid1  = gemmGrid - gemmGrid0;                        // 195

    // streams/events (intentionally leaked: kernel_launch called O(1) times)
    cudaStream_t s2;
    cudaStreamCreateWithFlags(&s2, cudaStreamNonBlocking);
    cudaEvent_t evFork, evJoin, eA0, eA1, eG1, eB0, eB1, eG2;
    cudaEventCreateWithFlags(&evFork, cudaEventDisableTiming);
    cudaEventCreateWithFlags(&evJoin, cudaEventDisableTiming);
    cudaEventCreateWithFlags(&eA0, cudaEventDisableTiming);
    cudaEventCreateWithFlags(&eA1, cudaEventDisableTiming);
    cudaEventCreateWithFlags(&eG1, cudaEventDisableTiming);
    cudaEventCreateWithFlags(&eB0, cudaEventDisableTiming);
    cudaEventCreateWithFlags(&eB1, cudaEventDisableTiming);
    cudaEventCreateWithFlags(&eG2, cudaEventDisableTiming);

    cudaEventRecord(evFork, 0);
    cudaStreamWaitEvent(s2, evFork, 0);

    // s2: CSR build chain (independent of cvt_w + gemm0 on default)
    zero_kernel<<<nodeBlocks, T, 0, s2>>>();
    deg_count_kernel<<<edgeBlocks, T, 0, s2>>>(dst);
    scan_bsum_kernel<<<NB_SCAN, 256, 0, s2>>>();       // also computes dinv
    scan_boff_kernel<<<1, 256, 0, s2>>>();
    scan_apply_kernel<<<NB_SCAN, 256, 0, s2>>>();
    scatter_kernel<<<edgeBlocks, T, 0, s2>>>(src, dst);
    cudaEventRecord(evJoin, s2);

    // default: weight conversion + layer-0 GEMM (reads fp32 x directly)
    cvt_w_kernel<<<(IN_CH * HID + T - 1) / T, T>>>(W0, W1, W2);
    gemm_f16_kernel<true><<<gemmGrid, 512, GEMM_SMEM_F32>>>(IN_CH, 0, x, p_w0h, p_h);

    // join: aggregation needs CSR + gemm0
    cudaStreamWaitEvent(0, evJoin, 0);

    // ---- layer 1: chunk-pipelined agg -> gemm ----
    agg_relu_kernel<<<aggBlocks0, T>>>(0, CHUNK, p_h, b0, p_in);
    cudaEventRecord(eA0, 0);
    agg_relu_kernel<<<aggBlocks1, T>>>(CHUNK, N_NODES, p_h, b0, p_in);
    cudaEventRecord(eA1, 0);

    cudaStreamWaitEvent(s2, eA0, 0);
    gemm_f16_kernel<false><<<gemmGrid0, 512, GEMM_SMEM_F16, s2>>>(HID, 0, p_in, p_w1h, p_h);
    cudaStreamWaitEvent(s2, eA1, 0);
    gemm_f16_kernel<false><<<gemmGrid1, 512, GEMM_SMEM_F16, s2>>>(HID, CHUNK, p_in, p_w1h, p_h);
    cudaEventRecord(eG1, s2);

    // ---- layer 2: chunk-pipelined agg -> gemm ----
    cudaStreamWaitEvent(0, eG1, 0);
    agg_relu_kernel<<<aggBlocks0, T>>>(0, CHUNK, p_h, b1, p_in);
    cudaEventRecord(eB0, 0);
    agg_relu_kernel<<<aggBlocks1, T>>>(CHUNK, N_NODES, p_h, b1, p_in);
    cudaEventRecord(eB1, 0);

    cudaStreamWaitEvent(s2, eB0, 0);
    gemm_f16_kernel<false><<<gemmGrid0, 512, GEMM_SMEM_F16, s2>>>(HID, 0, p_in, p_w2h, p_h);
    cudaStreamWaitEvent(s2, eB1, 0);
    gemm_f16_kernel<false><<<gemmGrid1, 512, GEMM_SMEM_F16, s2>>>(HID, CHUNK, p_in, p_w2h, p_h);
    cudaEventRecord(eG2, s2);

    // ---- final readout ----
    cudaStreamWaitEvent(0, eG2, 0);
    agg_readout_kernel<<<warpBlocks, T>>>(p_h, b2, Wout, bout, out);
}

// round 17
// speedup vs baseline: 1.1374x; 1.1374x over previous
#include <cuda_runtime.h>
#include <cuda_fp16.h>
#include <cstdint>

#define N_NODES 50000
#define N_EDGES 800000
#define IN_CH   512
#define HID     256

// ---------------- scratch (no allocations allowed) ----------------
#define NB_SCAN ((N_NODES + 255) / 256)   // 196

__device__ int      g_degi  [N_NODES];
__device__ float    g_dinv  [N_NODES];
__device__ int      g_rowptr[N_NODES + 1];
__device__ int      g_fill  [N_NODES];
__device__ int      g_bsum  [NB_SCAN];
__device__ int      g_boff  [NB_SCAN];
__device__ int2     g_epack [N_EDGES];                   // {src, norm bits}
__device__ __half   g_w0h   [IN_CH * HID];               // fp16 W0^T  [n][k]
__device__ __half   g_w1h   [HID * HID];                 // fp16 W1^T
__device__ __half   g_w2h   [HID * HID];                 // fp16 W2^T
__device__ __half   g_h     [(size_t)N_NODES * HID];     // GEMM output (gather operand)
__device__ __half   g_in    [(size_t)N_NODES * HID];     // fp16 relu(agg+b)

// ---------------- degree / norm / CSR build ----------------
__global__ void zero_kernel() {
    int i = blockIdx.x * blockDim.x + threadIdx.x;
    if (i < N_NODES) { g_degi[i] = 0; g_fill[i] = 0; }
}

__global__ void deg_count_kernel(const int* __restrict__ dst) {
    int e = blockIdx.x * blockDim.x + threadIdx.x;
    if (e < N_EDGES) atomicAdd(&g_degi[__ldg(&dst[e])], 1);
}

// block sums for scan + dinv (deg final after deg_count)
__global__ void scan_bsum_kernel() {
    __shared__ int sh[256];
    int t = threadIdx.x;
    int i = blockIdx.x * 256 + t;
    int d = (i < N_NODES) ? g_degi[i] : 0;
    if (i < N_NODES) g_dinv[i] = rsqrtf((float)(d + 1));   // +1 self-loop
    sh[t] = d;
    __syncthreads();
    for (int off = 128; off > 0; off >>= 1) {
        if (t < off) sh[t] += sh[t + off];
        __syncthreads();
    }
    if (t == 0) g_bsum[blockIdx.x] = sh[0];
}

__global__ void scan_boff_kernel() {
    __shared__ int sh[256];
    int t = threadIdx.x;
    int v = (t < NB_SCAN) ? g_bsum[t] : 0;
    sh[t] = v;
    __syncthreads();
    for (int off = 1; off < 256; off <<= 1) {
        int u = (t >= off) ? sh[t - off] : 0;
        __syncthreads();
        sh[t] += u;
        __syncthreads();
    }
    if (t < NB_SCAN) g_boff[t] = sh[t] - v;
    if (t == 255) g_rowptr[N_NODES] = sh[255];
}

__global__ void scan_apply_kernel() {
    __shared__ int sh[256];
    int t = threadIdx.x;
    int i = blockIdx.x * 256 + t;
    int v = (i < N_NODES) ? g_degi[i] : 0;
    sh[t] = v;
    __syncthreads();
    for (int off = 1; off < 256; off <<= 1) {
        int u = (t >= off) ? sh[t - off] : 0;
        __syncthreads();
        sh[t] += u;
        __syncthreads();
    }
    if (i < N_NODES) g_rowptr[i] = g_boff[blockIdx.x] + sh[t] - v;
}

__global__ void scatter_kernel(const int* __restrict__ src,
                               const int* __restrict__ dst) {
    int e = blockIdx.x * blockDim.x + threadIdx.x;
    if (e < N_EDGES) {
        int s = __ldg(&src[e]);
        int d = __ldg(&dst[e]);
        int pos = g_rowptr[d] + atomicAdd(&g_fill[d], 1);
        g_epack[pos] = make_int2(s, __float_as_int(g_dinv[s] * g_dinv[d]));
    }
}

// ---------------- weight transpose + fp16 ----------------
__global__ void cvt_w_kernel(const float* __restrict__ W0,
                             const float* __restrict__ W1,
                             const float* __restrict__ W2) {
    int i = blockIdx.x * blockDim.x + threadIdx.x;
    if (i < IN_CH * HID) {
        int n = i / IN_CH, k = i % IN_CH;
        g_w0h[i] = __float2half(__ldg(&W0[k * HID + n]));
    }
    if (i < HID * HID) {
        int n = i / HID, k = i % HID;
        g_w1h[i] = __float2half(__ldg(&W1[k * HID + n]));
        g_w2h[i] = __float2half(__ldg(&W2[k * HID + n]));
    }
}

// ---------------- fp16 mma m16n8k16 + ldmatrix ----------------
__device__ __forceinline__ void mma_f16(float* c,
                                        uint32_t a0, uint32_t a1, uint32_t a2, uint32_t a3,
                                        uint32_t b0, uint32_t b1) {
    asm volatile(
        "mma.sync.aligned.m16n8k16.row.col.f32.f16.f16.f32 "
        "{%0,%1,%2,%3}, {%4,%5,%6,%7}, {%8,%9}, {%0,%1,%2,%3};"
        : "+f"(c[0]), "+f"(c[1]), "+f"(c[2]), "+f"(c[3])
        : "r"(a0), "r"(a1), "r"(a2), "r"(a3), "r"(b0), "r"(b1));
}

__device__ __forceinline__ void ldsm_x4(uint32_t* r, uint32_t addr) {
    asm volatile("ldmatrix.sync.aligned.m8n8.x4.shared.b16 {%0,%1,%2,%3}, [%4];"
                 : "=r"(r[0]), "=r"(r[1]), "=r"(r[2]), "=r"(r[3]) : "r"(addr));
}

#define GBM 128
#define GBK 32
#define TSH 40                                // halves per smem row (80 B), conflict-free
#define A_TILE_B (128 * TSH * 2)              // 10240
#define B_TILE_B (256 * TSH * 2)              // 20480

// ---------------- layer-0 GEMM (A = fp32 x), grid 391, as in round 14 ----------------
#define BBASE (3 * A_TILE_B)                  // 30720
#define SCR_BASE (BBASE + 3 * B_TILE_B)       // 92160
#define SCR_STRIDE 144                        // bytes per fp32 scratch row (16B mult)
#define SCR_TILE (128 * SCR_STRIDE)           // 18432
#define GEMM_SMEM_F32 (SCR_BASE + 3 * SCR_TILE)   // 147456

__global__ __launch_bounds__(512) void gemm0_kernel(
    const float* __restrict__ A32,    // [M, 512] fp32
    const __half* __restrict__ Wt,    // [256, 512]
    __half* __restrict__ Ch)          // [M, 256]
{
    extern __shared__ char smc[];
    const uint32_t sbase = (uint32_t)__cvta_generic_to_shared(smc);
    const int K = IN_CH;

    const int tid  = threadIdx.x;
    const int lane = tid & 31;
    const int warp = tid >> 5;
    const int wm   = warp >> 3;
    const int wn   = warp & 7;
    const int g    = lane >> 2;
    const int t    = lane & 3;
    const int lrow = lane & 7;
    const int lgrp = lane >> 3;

    const int crow0 = blockIdx.x * GBM;

    float acc[4][4][4];
#pragma unroll
    for (int fm = 0; fm < 4; fm++)
#pragma unroll
        for (int fn = 0; fn < 4; fn++)
#pragma unroll
            for (int q = 0; q < 4; q++) acc[fm][fn][q] = 0.0f;

    uint32_t aOff[4];
#pragma unroll
    for (int fm = 0; fm < 4; fm++)
        aOff[fm] = (uint32_t)(((wm * 64 + fm * 16 + ((lgrp & 1) << 3) + lrow) * TSH +
                               ((lgrp >> 1) << 3)) * 2);
    uint32_t bOff[2];
#pragma unroll
    for (int p = 0; p < 2; p++)
        bOff[p] = (uint32_t)(((wn * 32 + p * 16 + ((lgrp >> 1) << 3) + lrow) * TSH +
                              ((lgrp & 1) << 3)) * 2);

    auto stage = [&](int buf, int k0) {
#pragma unroll
        for (int i = 0; i < 2; i++) {
            int idx   = tid + i * 512;
            int row   = idx >> 3;
            int chunk = idx & 7;
            int grow  = crow0 + row;
            uint32_t dstp = sbase + (uint32_t)(SCR_BASE + buf * SCR_TILE + row * SCR_STRIDE + chunk * 16);
            const float* srcp = A32 + (size_t)(grow < N_NODES ? grow : 0) * K + k0 + chunk * 4;
            int sz = (grow < N_NODES) ? 16 : 0;
            asm volatile("cp.async.ca.shared.global [%0], [%1], 16, %2;"
                         :: "r"(dstp), "l"(srcp), "r"(sz));
        }
#pragma unroll
        for (int i = 0; i < 2; i++) {
            int idx   = tid + i * 512;
            int row   = idx >> 2;
            int chunk = idx & 3;
            uint32_t dstp = sbase + (uint32_t)(BBASE + buf * B_TILE_B + row * (TSH * 2) + chunk * 16);
            const __half* srcp = Wt + (size_t)row * K + k0 + chunk * 8;
            asm volatile("cp.async.ca.shared.global [%0], [%1], 16;"
                         :: "r"(dstp), "l"(srcp));
        }
        asm volatile("cp.async.commit_group;");
    };

    const int nk = K / GBK;        // 16
    stage(0, 0);
    stage(1, GBK);

    for (int ki = 0; ki < nk; ki++) {
        const int buf = ki % 3;
        if (ki + 1 < nk) {
            asm volatile("cp.async.wait_group 1;");
        } else {
            asm volatile("cp.async.wait_group 0;");
        }
        __syncthreads();

        // convert scratch fp32 -> fp16 A tile
        {
            int row   = tid >> 2;
            int chunk = tid & 3;
            const float* sp = reinterpret_cast<const float*>(smc + SCR_BASE + buf * SCR_TILE +
                                                             row * SCR_STRIDE) + chunk * 8;
            float4 v0 = *reinterpret_cast<const float4*>(sp);
            float4 v1 = *reinterpret_cast<const float4*>(sp + 4);
            __half2 h0 = __floats2half2_rn(v0.x, v0.y);
            __half2 h1 = __floats2half2_rn(v0.z, v0.w);
            __half2 h2 = __floats2half2_rn(v1.x, v1.y);
            __half2 h3 = __floats2half2_rn(v1.z, v1.w);
            uint4 u;
            u.x = *reinterpret_cast<uint32_t*>(&h0);
            u.y = *reinterpret_cast<uint32_t*>(&h1);
            u.z = *reinterpret_cast<uint32_t*>(&h2);
            u.w = *reinterpret_cast<uint32_t*>(&h3);
            *reinterpret_cast<uint4*>(smc + buf * A_TILE_B + row * (TSH * 2) + chunk * 16) = u;
            __syncthreads();
        }

        if (ki + 2 < nk) stage((ki + 2) % 3, (ki + 2) * GBK);

        const uint32_t aBase = sbase + (uint32_t)(buf * A_TILE_B);
        const uint32_t bBase = sbase + (uint32_t)(BBASE + buf * B_TILE_B);

#pragma unroll
        for (int kc = 0; kc < 2; kc++) {
            const uint32_t kb = kc * 32;
            uint32_t a[4][4];
            uint32_t b[2][4];
#pragma unroll
            for (int fm = 0; fm < 4; fm++) ldsm_x4(a[fm], aBase + aOff[fm] + kb);
#pragma unroll
            for (int p = 0; p < 2; p++)    ldsm_x4(b[p], bBase + bOff[p] + kb);
#pragma unroll
            for (int fm = 0; fm < 4; fm++)
#pragma unroll
                for (int fn = 0; fn < 4; fn++)
                    mma_f16(acc[fm][fn],
                            a[fm][0], a[fm][1], a[fm][2], a[fm][3],
                            b[fn >> 1][(fn & 1) * 2], b[fn >> 1][(fn & 1) * 2 + 1]);
        }
    }
    __syncthreads();

#pragma unroll
    for (int fm = 0; fm < 4; fm++) {
        int r0 = crow0 + wm * 64 + fm * 16 + g;
        int r1 = r0 + 8;
#pragma unroll
        for (int fn = 0; fn < 4; fn++) {
            int c = wn * 32 + fn * 8 + 2 * t;
            if (r0 < N_NODES)
                *reinterpret_cast<__half2*>(Ch + (size_t)r0 * HID + c) =
                    __floats2half2_rn(acc[fm][fn][0], acc[fm][fn][1]);
            if (r1 < N_NODES)
                *reinterpret_cast<__half2*>(Ch + (size_t)r1 * HID + c) =
                    __floats2half2_rn(acc[fm][fn][2], acc[fm][fn][3]);
        }
    }
}

// ---------------- persistent GEMM (layers 1-2, K=256): B fully smem-resident ----------------
// smem: A triple-buffer [0, 30720), B 8 chunks [30720, 194560)
#define BPERS (3 * A_TILE_B)                  // 30720
#define PERS_SMEM (BPERS + 8 * B_TILE_B)      // 194560
#define NTILES ((N_NODES + GBM - 1) / GBM)    // 391

__global__ __launch_bounds__(512) void gemm_pers_kernel(
    const __half* __restrict__ A16,   // [M, 256]
    const __half* __restrict__ Wt,    // [256, 256]
    __half* __restrict__ Ch)          // [M, 256]
{
    extern __shared__ char smc[];
    const uint32_t sbase = (uint32_t)__cvta_generic_to_shared(smc);
    const int K = HID;

    const int tid  = threadIdx.x;
    const int lane = tid & 31;
    const int warp = tid >> 5;
    const int wm   = warp >> 3;
    const int wn   = warp & 7;
    const int g    = lane >> 2;
    const int t    = lane & 3;
    const int lrow = lane & 7;
    const int lgrp = lane >> 3;

    uint32_t aOff[4];
#pragma unroll
    for (int fm = 0; fm < 4; fm++)
        aOff[fm] = (uint32_t)(((wm * 64 + fm * 16 + ((lgrp & 1) << 3) + lrow) * TSH +
                               ((lgrp >> 1) << 3)) * 2);
    uint32_t bOff[2];
#pragma unroll
    for (int p = 0; p < 2; p++)
        bOff[p] = (uint32_t)(((wn * 32 + p * 16 + ((lgrp >> 1) << 3) + lrow) * TSH +
                              ((lgrp & 1) << 3)) * 2);

    auto stageA = [&](int row0, int kc8, int buf) {
        int row   = tid >> 2;
        int chunk = tid & 3;
        int grow  = row0 + row;
        uint32_t dstp = sbase + (uint32_t)(buf * A_TILE_B + row * (TSH * 2) + chunk * 16);
        const __half* srcp = A16 + (size_t)(grow < N_NODES ? grow : 0) * K + kc8 * GBK + chunk * 8;
        int sz = (grow < N_NODES) ? 16 : 0;
        asm volatile("cp.async.ca.shared.global [%0], [%1], 16, %2;"
                     :: "r"(dstp), "l"(srcp), "r"(sz));
        asm volatile("cp.async.commit_group;");
    };

    // prologue: all 8 B chunks, ONE commit group (oldest group)
#pragma unroll
    for (int c = 0; c < 8; c++) {
#pragma unroll
        for (int i = 0; i < 2; i++) {
            int idx   = tid + i * 512;
            int row   = idx >> 2;
            int chunk = idx & 3;
            uint32_t dstp = sbase + (uint32_t)(BPERS + c * B_TILE_B + row * (TSH * 2) + chunk * 16);
            const __half* srcp = Wt + (size_t)row * K + c * GBK + chunk * 8;
            asm volatile("cp.async.ca.shared.global [%0], [%1], 16;"
                         :: "r"(dstp), "l"(srcp));
        }
    }
    asm volatile("cp.async.commit_group;");

    int tile = blockIdx.x;
    if (tile < NTILES) {
        stageA(tile * GBM, 0, 0);
        stageA(tile * GBM, 1, 1);
    }

    for (; tile < NTILES; tile += (int)gridDim.x) {
        const int crow0 = tile * GBM;

        float acc[4][4][4];
#pragma unroll
        for (int fm = 0; fm < 4; fm++)
#pragma unroll
            for (int fn = 0; fn < 4; fn++)
#pragma unroll
                for (int q = 0; q < 4; q++) acc[fm][fn][q] = 0.0f;

#pragma unroll 1
        for (int ki = 0; ki < 8; ki++) {
            const int buf = ki % 3;
            if (ki + 1 < 8) {
                asm volatile("cp.async.wait_group 1;");
            } else {
                asm volatile("cp.async.wait_group 0;");
            }
            __syncthreads();
            if (ki + 2 < 8) stageA(crow0, ki + 2, (ki + 2) % 3);

            const uint32_t aBase = sbase + (uint32_t)(buf * A_TILE_B);
            const uint32_t bBase = sbase + (uint32_t)(BPERS + ki * B_TILE_B);

#pragma unroll
            for (int kc = 0; kc < 2; kc++) {
                const uint32_t kb = kc * 32;
                uint32_t a[4][4];
                uint32_t b[2][4];
#pragma unroll
                for (int fm = 0; fm < 4; fm++) ldsm_x4(a[fm], aBase + aOff[fm] + kb);
#pragma unroll
                for (int p = 0; p < 2; p++)    ldsm_x4(b[p], bBase + bOff[p] + kb);
#pragma unroll
                for (int fm = 0; fm < 4; fm++)
#pragma unroll
                    for (int fn = 0; fn < 4; fn++)
                        mma_f16(acc[fm][fn],
                                a[fm][0], a[fm][1], a[fm][2], a[fm][3],
                                b[fn >> 1][(fn & 1) * 2], b[fn >> 1][(fn & 1) * 2 + 1]);
            }
        }
        __syncthreads();   // all warps done reading A buffers before restaging

        // prime next tile's pipeline, overlapping with this epilogue
        int ntile = tile + (int)gridDim.x;
        if (ntile < NTILES) {
            stageA(ntile * GBM, 0, 0);
            stageA(ntile * GBM, 1, 1);
        }

#pragma unroll
        for (int fm = 0; fm < 4; fm++) {
            int r0 = crow0 + wm * 64 + fm * 16 + g;
            int r1 = r0 + 8;
#pragma unroll
            for (int fn = 0; fn < 4; fn++) {
                int c = wn * 32 + fn * 8 + 2 * t;
                if (r0 < N_NODES)
                    *reinterpret_cast<__half2*>(Ch + (size_t)r0 * HID + c) =
                        __floats2half2_rn(acc[fm][fn][0], acc[fm][fn][1]);
                if (r1 < N_NODES)
                    *reinterpret_cast<__half2*>(Ch + (size_t)r1 * HID + c) =
                        __floats2half2_rn(acc[fm][fn][2], acc[fm][fn][3]);
            }
        }
    }
}

// ---------------- CSR gather (packed edges, 4x-unrolled) ----------------
__device__ __forceinline__ void agg_node(int node, const __half* __restrict__ h,
                                         int lane, float acc[8]) {
#pragma unroll
    for (int q = 0; q < 8; q++) acc[q] = 0.0f;

    int p0 = g_rowptr[node];
    int p1 = g_rowptr[node + 1];
    for (int base = p0; base < p1; base += 32) {
        int nn = min(32, p1 - base);
        int2 ep = make_int2(0, 0);
        if (base + lane < p1) ep = __ldg(&g_epack[base + lane]);
        int   sv = ep.x;
        float nv = __int_as_float(ep.y);

        int j = 0;
        for (; j + 4 <= nn; j += 4) {
            int   s0 = __shfl_sync(0xffffffffu, sv, j);
            int   s1 = __shfl_sync(0xffffffffu, sv, j + 1);
            int   s2 = __shfl_sync(0xffffffffu, sv, j + 2);
            int   s3 = __shfl_sync(0xffffffffu, sv, j + 3);
            float n0 = __shfl_sync(0xffffffffu, nv, j);
            float n1 = __shfl_sync(0xffffffffu, nv, j + 1);
            float n2 = __shfl_sync(0xffffffffu, nv, j + 2);
            float n3 = __shfl_sync(0xffffffffu, nv, j + 3);
            uint4 r0 = __ldg(reinterpret_cast<const uint4*>(h + (size_t)s0 * HID) + lane);
            uint4 r1 = __ldg(reinterpret_cast<const uint4*>(h + (size_t)s1 * HID) + lane);
            uint4 r2 = __ldg(reinterpret_cast<const uint4*>(h + (size_t)s2 * HID) + lane);
            uint4 r3 = __ldg(reinterpret_cast<const uint4*>(h + (size_t)s3 * HID) + lane);
            const __half2* v0 = reinterpret_cast<const __half2*>(&r0);
            const __half2* v1 = reinterpret_cast<const __half2*>(&r1);
            const __half2* v2 = reinterpret_cast<const __half2*>(&r2);
            const __half2* v3 = reinterpret_cast<const __half2*>(&r3);
#pragma unroll
            for (int q = 0; q < 4; q++) {
                float2 f0 = __half22float2(v0[q]);
                float2 f1 = __half22float2(v1[q]);
                float2 f2 = __half22float2(v2[q]);
                float2 f3 = __half22float2(v3[q]);
                acc[2 * q + 0] = fmaf(n0, f0.x, fmaf(n1, f1.x, fmaf(n2, f2.x, fmaf(n3, f3.x, acc[2 * q + 0]))));
                acc[2 * q + 1] = fmaf(n0, f0.y, fmaf(n1, f1.y, fmaf(n2, f2.y, fmaf(n3, f3.y, acc[2 * q + 1]))));
            }
        }
        for (; j < nn; j++) {
            int   s   = __shfl_sync(0xffffffffu, sv, j);
            float nrm = __shfl_sync(0xffffffffu, nv, j);
            uint4 raw = __ldg(reinterpret_cast<const uint4*>(h + (size_t)s * HID) + lane);
            const __half2* hv = reinterpret_cast<const __half2*>(&raw);
#pragma unroll
            for (int q = 0; q < 4; q++) {
                float2 f = __half22float2(hv[q]);
                acc[2 * q + 0] = fmaf(nrm, f.x, acc[2 * q + 0]);
                acc[2 * q + 1] = fmaf(nrm, f.y, acc[2 * q + 1]);
            }
        }
    }
    // self-loop
    float d = g_dinv[node];
    float w = d * d;
    uint4 raw = __ldg(reinterpret_cast<const uint4*>(h + (size_t)node * HID) + lane);
    const __half2* hv = reinterpret_cast<const __half2*>(&raw);
#pragma unroll
    for (int q = 0; q < 4; q++) {
        float2 f = __half22float2(hv[q]);
        acc[2 * q + 0] = fmaf(w, f.x, acc[2 * q + 0]);
        acc[2 * q + 1] = fmaf(w, f.y, acc[2 * q + 1]);
    }
}

// out = fp16(relu(agg + b))   (consumed only by next GEMM)
__global__ void agg_relu_kernel(const __half* __restrict__ h,
                                const float* __restrict__ b,
                                __half* __restrict__ outbuf) {
    int gtid = blockIdx.x * blockDim.x + threadIdx.x;
    int node = gtid >> 5;
    int lane = threadIdx.x & 31;
    if (node >= N_NODES) return;

    float acc[8];
    agg_node(node, h, lane, acc);

    const float4* bp = reinterpret_cast<const float4*>(b);
    float4 b0 = __ldg(&bp[2 * lane]);
    float4 b1 = __ldg(&bp[2 * lane + 1]);

    __half2 h0 = __floats2half2_rn(fmaxf(acc[0] + b0.x, 0.f), fmaxf(acc[1] + b0.y, 0.f));
    __half2 h1 = __floats2half2_rn(fmaxf(acc[2] + b0.z, 0.f), fmaxf(acc[3] + b0.w, 0.f));
    __half2 h2 = __floats2half2_rn(fmaxf(acc[4] + b1.x, 0.f), fmaxf(acc[5] + b1.y, 0.f));
    __half2 h3 = __floats2half2_rn(fmaxf(acc[6] + b1.z, 0.f), fmaxf(acc[7] + b1.w, 0.f));

    uint4 u;
    u.x = *reinterpret_cast<uint32_t*>(&h0);
    u.y = *reinterpret_cast<uint32_t*>(&h1);
    u.z = *reinterpret_cast<uint32_t*>(&h2);
    u.w = *reinterpret_cast<uint32_t*>(&h3);
    reinterpret_cast<uint4*>(outbuf + (size_t)node * HID)[lane] = u;
}

__global__ void agg_readout_kernel(const __half* __restrict__ h,
                                   const float* __restrict__ b,
                                   const float* __restrict__ Wout,
                                   const float* __restrict__ bout,
                                   float* __restrict__ out) {
    int gtid = blockIdx.x * blockDim.x + threadIdx.x;
    int node = gtid >> 5;
    int lane = threadIdx.x & 31;
    if (node >= N_NODES) return;

    float acc[8];
    agg_node(node, h, lane, acc);

    const float4* bp = reinterpret_cast<const float4*>(b);
    const float4* wp = reinterpret_cast<const float4*>(Wout);
    float4 b0 = __ldg(&bp[2 * lane]);
    float4 b1 = __ldg(&bp[2 * lane + 1]);
    float4 w0 = __ldg(&wp[2 * lane]);
    float4 w1 = __ldg(&wp[2 * lane + 1]);

    float s = fmaxf(acc[0] + b0.x, 0.f) * w0.x + fmaxf(acc[1] + b0.y, 0.f) * w0.y +
              fmaxf(acc[2] + b0.z, 0.f) * w0.z + fmaxf(acc[3] + b0.w, 0.f) * w0.w +
              fmaxf(acc[4] + b1.x, 0.f) * w1.x + fmaxf(acc[5] + b1.y, 0.f) * w1.y +
              fmaxf(acc[6] + b1.z, 0.f) * w1.z + fmaxf(acc[7] + b1.w, 0.f) * w1.w;
#pragma unroll
    for (int o = 16; o > 0; o >>= 1) s += __shfl_down_sync(0xffffffffu, s, o);
    if (lane == 0) out[node] = s + __ldg(&bout[0]);
}

// ---------------- host launcher ----------------
extern "C" void kernel_launch(void* const* d_in, const int* in_sizes, int n_in,
                              void* d_out, int out_size) {
    const float* x    = (const float*)d_in[0];
    const int*   ei   = (const int*)d_in[1];   // delivered as int32
    const float* W0   = (const float*)d_in[2];
    const float* b0   = (const float*)d_in[3];
    const float* W1   = (const float*)d_in[4];
    const float* b1   = (const float*)d_in[5];
    const float* W2   = (const float*)d_in[6];
    const float* b2   = (const float*)d_in[7];
    const float* Wout = (const float*)d_in[8];
    const float* bout = (const float*)d_in[9];
    float*       out  = (float*)d_out;

    const int* src = ei;             // edge_index[0]
    const int* dst = ei + N_EDGES;   // edge_index[1]

    __half *p_h, *p_in, *p_w0h, *p_w1h, *p_w2h;
    cudaGetSymbolAddress((void**)&p_h,   g_h);
    cudaGetSymbolAddress((void**)&p_in,  g_in);
    cudaGetSymbolAddress((void**)&p_w0h, g_w0h);
    cudaGetSymbolAddress((void**)&p_w1h, g_w1h);
    cudaGetSymbolAddress((void**)&p_w2h, g_w2h);
    (void)in_sizes; (void)n_in; (void)out_size;

    cudaFuncSetAttribute(gemm0_kernel,
                         cudaFuncAttributeMaxDynamicSharedMemorySize, GEMM_SMEM_F32);
    cudaFuncSetAttribute(gemm_pers_kernel,
                         cudaFuncAttributeMaxDynamicSharedMemorySize, PERS_SMEM);

    const int T = 256;
    const int nodeBlocks = (N_NODES + T - 1) / T;
    const int edgeBlocks = (N_EDGES + T - 1) / T;
    const int warpBlocks = (N_NODES * 32 + T - 1) / T;
    const int gemmGrid   = NTILES;          // 391 (layer 0)
    const int persGrid   = 152;             // GB300 SM count

    // Fork: CSR build on s2, cvt_w + layer-0 GEMM on default stream (independent)
    cudaStream_t s2;
    cudaStreamCreateWithFlags(&s2, cudaStreamNonBlocking);
    cudaEvent_t evFork, evJoin;
    cudaEventCreateWithFlags(&evFork, cudaEventDisableTiming);
    cudaEventCreateWithFlags(&evJoin, cudaEventDisableTiming);
    // (stream/events intentionally leaked: kernel_launch is called O(1) times)

    cudaEventRecord(evFork, 0);
    cudaStreamWaitEvent(s2, evFork, 0);

    // s2: CSR build chain
    zero_kernel<<<nodeBlocks, T, 0, s2>>>();
    deg_count_kernel<<<edgeBlocks, T, 0, s2>>>(dst);
    scan_bsum_kernel<<<NB_SCAN, 256, 0, s2>>>();       // also computes dinv
    scan_boff_kernel<<<1, 256, 0, s2>>>();
    scan_apply_kernel<<<NB_SCAN, 256, 0, s2>>>();
    scatter_kernel<<<edgeBlocks, T, 0, s2>>>(src, dst);
    cudaEventRecord(evJoin, s2);

    // default stream: weight conversion + layer-0 GEMM (reads fp32 x directly)
    cvt_w_kernel<<<(IN_CH * HID + T - 1) / T, T>>>(W0, W1, W2);
    gemm0_kernel<<<gemmGrid, 512, GEMM_SMEM_F32>>>(x, p_w0h, p_h);

    // join: aggregation needs CSR + gemm0
    cudaStreamWaitEvent(0, evJoin, 0);
    agg_relu_kernel<<<warpBlocks, T>>>(p_h, b0, p_in);

    // layer 1 (persistent, B-resident)
    gemm_pers_kernel<<<persGrid, 512, PERS_SMEM>>>(p_in, p_w1h, p_h);
    agg_relu_kernel<<<warpBlocks, T>>>(p_h, b1, p_in);

    // layer 2 + fused readout
    gemm_pers_kernel<<<persGrid, 512, PERS_SMEM>>>(p_in, p_w2h, p_h);
    agg_readout_kernel<<<warpBlocks, T>>>(p_h, b2, Wout, bout, out);
}